// round 11
// baseline (speedup 1.0000x reference)
#include <cuda_runtime.h>
#include <cuda_bf16.h>
#include <cstdint>

// Problem constants (fixed by the dataset)
#define Bn 4
#define Nn 10000
#define Dn 64
#define Cn 2
#define En 160000
#define EPSc 1e-10f
#define BCn (Bn * Cn)
#define CAP 64           // bucket capacity per destination node (mean count = 16)

// Static scratch (no allocation allowed)
__device__ float  g_s1[BCn * Nn];              // node scores (dst half)
__device__ float  g_s2[BCn * Nn];              // node scores (src half)
__device__ float  g_denom[BCn * Nn];           // segment sum of e by idx0
__device__ float  g_rdenom[BCn * Nn];          // 1 / (denom + eps)
__device__ int    g_cnt[BCn * Nn];             // edges per destination node
__device__ float2 g_bucket[(size_t)BCn * Nn * CAP];  // (idx1 bits, e) slots (41 MB)

__device__ __forceinline__ float fast_tanh(float x) {
    float y;
    asm("tanh.approx.f32 %0, %1;" : "=f"(y) : "f"(x));
    return y;
}
__device__ __forceinline__ float fast_sigmoid(float x) {
    return 0.5f * fast_tanh(0.5f * x) + 0.5f;
}
// clamp any data-derived index into [0, Nn)
__device__ __forceinline__ int clamp_idx(int i) {
    unsigned u = (unsigned)i;
    return (u < (unsigned)Nn) ? (int)u : 0;
}

// ---------------------------------------------------------------------------
// K1: per-node scores; also zeroes denom/cnt (first 80K threads).
__global__ void scores_kernel(const float* __restrict__ x,
                              const float* __restrict__ wa) {
    int tg = blockIdx.x * blockDim.x + threadIdx.x;
    if (tg < BCn * Nn) {                     // fused zero pass
        g_denom[tg] = 0.f;
        g_cnt[tg] = 0;
    }
    int w = tg >> 5;
    int lane = threadIdx.x & 31;
    if (w >= Bn * Nn) return;
    int b = w / Nn;
    int n = w - b * Nn;

    float2 xv = reinterpret_cast<const float2*>(x + (size_t)(b * Nn + n) * Dn)[lane];

#pragma unroll
    for (int c = 0; c < Cn; c++) {
        float2 w1 = reinterpret_cast<const float2*>(wa + c * 2 * Dn)[lane];
        float2 w2 = reinterpret_cast<const float2*>(wa + c * 2 * Dn + Dn)[lane];
        float p1 = xv.x * w1.x + xv.y * w1.y;
        float p2 = xv.x * w2.x + xv.y * w2.y;
#pragma unroll
        for (int o = 16; o; o >>= 1) {
            p1 += __shfl_xor_sync(0xffffffffu, p1, o);
            p2 += __shfl_xor_sync(0xffffffffu, p2, o);
        }
        if (lane == 0) {
            g_s1[(b * Cn + c) * Nn + n] = p1;
            g_s2[(b * Cn + c) * Nn + n] = p2;
        }
    }
}

// ---------------------------------------------------------------------------
// K2: single edge pass: exp, denom accumulation, and bucket placement.
// All indices clamped before use.
__global__ void edge_kernel(const int2* __restrict__ ep) {
    int t = blockIdx.x * blockDim.x + threadIdx.x;
    if (t >= BCn * En) return;
    int bc = t / En;
    int2 p = ep[t];                         // p.x = idx0 (dst), p.y = idx1 (src)
    int i0 = clamp_idx(p.x);
    int i1 = clamp_idx(p.y);
    float sc = g_s1[bc * Nn + i1] + g_s2[bc * Nn + i0];
    sc = sc >= 0.f ? sc : 0.2f * sc;        // leaky_relu(0.2)
    float ev = __expf(sc);
    int node = bc * Nn + i0;
    atomicAdd(&g_denom[node], ev);
    int pos = atomicAdd(&g_cnt[node], 1);
    if (pos < CAP)                          // overflow prob ~1e-24; safety clamp
        g_bucket[((size_t)node << 6) + pos] = make_float2(__int_as_float(i1), ev);
}

// ---------------------------------------------------------------------------
// K2b: reciprocal table: rdenom = 1 / (denom + eps). 80K threads, ~2us.
__global__ void rcp_kernel() {
    int t = blockIdx.x * blockDim.x + threadIdx.x;
    if (t < BCn * Nn)
        g_rdenom[t] = __fdividef(1.f, g_denom[t] + EPSc);
}

// ---------------------------------------------------------------------------
// K3: gather + sigmoid. 16 lanes per (b, n). NO shuffles, NO division:
// every lane broadcast-loads the pair and multiplies by the rdenom table.
// Every data-derived index is clamped before forming an address.
__global__ void gather_kernel(const float* __restrict__ x,
                              float* __restrict__ out) {
    int t = blockIdx.x * blockDim.x + threadIdx.x;   // 640,000 threads
    int g = t >> 4;                                  // (b, n) group
    if (g >= Bn * Nn) return;
    int seg = t & 15;
    int b = g / Nn;
    int n = g - b * Nn;
    const float4* x4 = reinterpret_cast<const float4*>(x) + (size_t)b * Nn * 16;

    float4 res[Cn];
#pragma unroll
    for (int c = 0; c < Cn; c++) {
        int bc = b * Cn + c;
        int node = bc * Nn + n;
        int cnt = min(max(g_cnt[node], 0), CAP);     // clamp to [0, CAP]
        const float2* pairs = g_bucket + ((size_t)node << 6);
        const float* rden = g_rdenom + bc * Nn;

        float4 acc0 = make_float4(0.f, 0.f, 0.f, 0.f);
        float4 acc1 = make_float4(0.f, 0.f, 0.f, 0.f);

        for (int base = 0; base < cnt; base += 16) {
#pragma unroll
            for (int k = 0; k < 16; k++) {
                bool pred = (base + k < cnt);
                // slot select stays in [0, CAP); load result discarded if !pred
                float2 pr = pairs[pred ? base + k : 0];
                int i1 = clamp_idx(__float_as_int(pr.x));   // hard clamp [0, Nn)
                float al = pred ? pr.y * rden[i1] : 0.f;
                float4 xv = x4[(size_t)i1 * 16 + seg];
                if (k & 1) {
                    acc1.x = fmaf(al, xv.x, acc1.x);
                    acc1.y = fmaf(al, xv.y, acc1.y);
                    acc1.z = fmaf(al, xv.z, acc1.z);
                    acc1.w = fmaf(al, xv.w, acc1.w);
                } else {
                    acc0.x = fmaf(al, xv.x, acc0.x);
                    acc0.y = fmaf(al, xv.y, acc0.y);
                    acc0.z = fmaf(al, xv.z, acc0.z);
                    acc0.w = fmaf(al, xv.w, acc0.w);
                }
            }
        }
        res[c] = make_float4(acc0.x + acc1.x, acc0.y + acc1.y,
                             acc0.z + acc1.z, acc0.w + acc1.w);
    }

    float4 o;
    o.x = fast_sigmoid(res[0].x) + fast_sigmoid(res[1].x);
    o.y = fast_sigmoid(res[0].y) + fast_sigmoid(res[1].y);
    o.z = fast_sigmoid(res[0].z) + fast_sigmoid(res[1].z);
    o.w = fast_sigmoid(res[0].w) + fast_sigmoid(res[1].w);
    reinterpret_cast<float4*>(out)[(size_t)g * 16 + seg] = o;
}

// ---------------------------------------------------------------------------
extern "C" void kernel_launch(void* const* d_in, const int* in_sizes, int n_in,
                              void* d_out, int out_size) {
    const float* x  = (const float*)d_in[0];   // (B, N, D) f32
    const int2*  ep = (const int2*) d_in[1];   // (B, C, E, 2) i32 -> int2 pairs
    const float* wa = (const float*)d_in[2];   // (C, 2D, 1) f32
    float* out = (float*)d_out;                // (B, N, D) f32

    scores_kernel<<<(Bn * Nn * 32 + 255) / 256, 256>>>(x, wa);
    edge_kernel<<<(BCn * En + 255) / 256, 256>>>(ep);
    rcp_kernel<<<(BCn * Nn + 255) / 256, 256>>>();
    gather_kernel<<<(Bn * Nn * 16 + 255) / 256, 256>>>(x, out);
}

// round 12
// speedup vs baseline: 1.1939x; 1.1939x over previous
#include <cuda_runtime.h>
#include <cuda_bf16.h>
#include <cstdint>

// Problem constants (fixed by the dataset)
#define Bn 4
#define Nn 10000
#define Dn 64
#define Cn 2
#define En 160000
#define EPSc 1e-10f
#define BCn (Bn * Cn)
#define CAP 64           // bucket capacity per destination node (mean count = 16)

// Static scratch (no allocation allowed)
__device__ float  g_s1[BCn * Nn];              // node scores (dst half)
__device__ float  g_s2[BCn * Nn];              // node scores (src half)
__device__ float  g_denom[BCn * Nn];           // segment sum of e by idx0
__device__ float  g_rdenom[BCn * Nn];          // 1 / (denom + eps)
__device__ int    g_cnt[BCn * Nn];             // edges per destination node
__device__ float2 g_bucket[(size_t)BCn * Nn * CAP];  // (idx1 bits, e) slots (41 MB)

__device__ __forceinline__ float fast_tanh(float x) {
    float y;
    asm("tanh.approx.f32 %0, %1;" : "=f"(y) : "f"(x));
    return y;
}
__device__ __forceinline__ float fast_sigmoid(float x) {
    return 0.5f * fast_tanh(0.5f * x) + 0.5f;
}
// clamp any data-derived index into [0, Nn)
__device__ __forceinline__ int clamp_idx(int i) {
    unsigned u = (unsigned)i;
    return (u < (unsigned)Nn) ? (int)u : 0;
}

// ---------------------------------------------------------------------------
// K1: per-node scores; also zeroes denom/cnt (first 80K threads).
__global__ void scores_kernel(const float* __restrict__ x,
                              const float* __restrict__ wa) {
    int tg = blockIdx.x * blockDim.x + threadIdx.x;
    if (tg < BCn * Nn) {                     // fused zero pass
        g_denom[tg] = 0.f;
        g_cnt[tg] = 0;
    }
    int w = tg >> 5;
    int lane = threadIdx.x & 31;
    if (w >= Bn * Nn) return;
    int b = w / Nn;
    int n = w - b * Nn;

    float2 xv = reinterpret_cast<const float2*>(x + (size_t)(b * Nn + n) * Dn)[lane];

#pragma unroll
    for (int c = 0; c < Cn; c++) {
        float2 w1 = reinterpret_cast<const float2*>(wa + c * 2 * Dn)[lane];
        float2 w2 = reinterpret_cast<const float2*>(wa + c * 2 * Dn + Dn)[lane];
        float p1 = xv.x * w1.x + xv.y * w1.y;
        float p2 = xv.x * w2.x + xv.y * w2.y;
#pragma unroll
        for (int o = 16; o; o >>= 1) {
            p1 += __shfl_xor_sync(0xffffffffu, p1, o);
            p2 += __shfl_xor_sync(0xffffffffu, p2, o);
        }
        if (lane == 0) {
            g_s1[(b * Cn + c) * Nn + n] = p1;
            g_s2[(b * Cn + c) * Nn + n] = p2;
        }
    }
}

// ---------------------------------------------------------------------------
// K2: single edge pass: exp, denom accumulation, and bucket placement.
__global__ void edge_kernel(const int2* __restrict__ ep) {
    int t = blockIdx.x * blockDim.x + threadIdx.x;
    if (t >= BCn * En) return;
    int bc = t / En;
    int2 p = ep[t];                         // p.x = idx0 (dst), p.y = idx1 (src)
    int i0 = clamp_idx(p.x);
    int i1 = clamp_idx(p.y);
    float sc = g_s1[bc * Nn + i1] + g_s2[bc * Nn + i0];
    sc = sc >= 0.f ? sc : 0.2f * sc;        // leaky_relu(0.2)
    float ev = __expf(sc);
    int node = bc * Nn + i0;
    atomicAdd(&g_denom[node], ev);
    int pos = atomicAdd(&g_cnt[node], 1);
    if (pos < CAP)                          // overflow prob ~1e-24; safety clamp
        g_bucket[((size_t)node << 6) + pos] = make_float2(__int_as_float(i1), ev);
}

// ---------------------------------------------------------------------------
// K2b: reciprocal table: rdenom = 1 / (denom + eps). 80K threads, ~2us.
__global__ void rcp_kernel() {
    int t = blockIdx.x * blockDim.x + threadIdx.x;
    if (t < BCn * Nn)
        g_rdenom[t] = __fdividef(1.f, g_denom[t] + EPSc);
}

// ---------------------------------------------------------------------------
// K3: gather + sigmoid. Block = 256 threads = 16 groups x 16 lanes.
// Phase 1: stage (i1, alpha) for BOTH channels into smem (zero-padded).
// Phase 2: branch-free fused loop over both channels; hot loop has only
// LDS (group-broadcast) + LDG.128 + FMA. No shfl, no div, no clamp in loop.
__global__ __launch_bounds__(256) void gather_kernel(const float* __restrict__ x,
                                                     float* __restrict__ out) {
    __shared__ float2 sh[16][Cn][CAP];               // 16 KB
    int t = blockIdx.x * blockDim.x + threadIdx.x;   // 640,000 threads
    int g = t >> 4;                                  // (b, n) group (exactly 40000)
    int seg = t & 15;
    int gl = threadIdx.x >> 4;                       // local group 0..15
    int b = g / Nn;
    int n = g - b * Nn;
    const float4* x4 = reinterpret_cast<const float4*>(x) + (size_t)b * Nn * 16;

    // ---- Phase 1: stage pairs with precomputed alpha ----
    int cnt[Cn];
#pragma unroll
    for (int c = 0; c < Cn; c++) {
        int node = (b * Cn + c) * Nn + n;
        int cc = min(max(g_cnt[node], 0), CAP);
        cnt[c] = cc;
        const float2* pairs = g_bucket + ((size_t)node << 6);
        const float* rden = g_rdenom + (b * Cn + c) * Nn;
#pragma unroll
        for (int j = 0; j < 4; j++) {
            int slot = seg + j * 16;
            float2 st = make_float2(__int_as_float(0), 0.f);
            if (slot < cc) {
                float2 pr = pairs[slot];
                int i1 = clamp_idx(__float_as_int(pr.x));
                st = make_float2(__int_as_float(i1), pr.y * rden[i1]);
            }
            sh[gl][c][slot] = st;
        }
    }
    __syncthreads();

    // ---- Phase 2: branch-free gather ----
    int maxc = max(cnt[0], cnt[1]);
    float4 a0e = make_float4(0.f, 0.f, 0.f, 0.f);
    float4 a0o = make_float4(0.f, 0.f, 0.f, 0.f);
    float4 a1e = make_float4(0.f, 0.f, 0.f, 0.f);
    float4 a1o = make_float4(0.f, 0.f, 0.f, 0.f);

    for (int base = 0; base < maxc; base += 4) {
#pragma unroll
        for (int k = 0; k < 4; k++) {
            // channel 0
            float2 p0 = sh[gl][0][base + k];
            float4 v0 = x4[(size_t)__float_as_int(p0.x) * 16 + seg];
            // channel 1
            float2 p1 = sh[gl][1][base + k];
            float4 v1 = x4[(size_t)__float_as_int(p1.x) * 16 + seg];
            if (k & 1) {
                a0o.x = fmaf(p0.y, v0.x, a0o.x);
                a0o.y = fmaf(p0.y, v0.y, a0o.y);
                a0o.z = fmaf(p0.y, v0.z, a0o.z);
                a0o.w = fmaf(p0.y, v0.w, a0o.w);
                a1o.x = fmaf(p1.y, v1.x, a1o.x);
                a1o.y = fmaf(p1.y, v1.y, a1o.y);
                a1o.z = fmaf(p1.y, v1.z, a1o.z);
                a1o.w = fmaf(p1.y, v1.w, a1o.w);
            } else {
                a0e.x = fmaf(p0.y, v0.x, a0e.x);
                a0e.y = fmaf(p0.y, v0.y, a0e.y);
                a0e.z = fmaf(p0.y, v0.z, a0e.z);
                a0e.w = fmaf(p0.y, v0.w, a0e.w);
                a1e.x = fmaf(p1.y, v1.x, a1e.x);
                a1e.y = fmaf(p1.y, v1.y, a1e.y);
                a1e.z = fmaf(p1.y, v1.z, a1e.z);
                a1e.w = fmaf(p1.y, v1.w, a1e.w);
            }
        }
    }

    float4 r0 = make_float4(a0e.x + a0o.x, a0e.y + a0o.y,
                            a0e.z + a0o.z, a0e.w + a0o.w);
    float4 r1 = make_float4(a1e.x + a1o.x, a1e.y + a1o.y,
                            a1e.z + a1o.z, a1e.w + a1o.w);

    float4 o;
    o.x = fast_sigmoid(r0.x) + fast_sigmoid(r1.x);
    o.y = fast_sigmoid(r0.y) + fast_sigmoid(r1.y);
    o.z = fast_sigmoid(r0.z) + fast_sigmoid(r1.z);
    o.w = fast_sigmoid(r0.w) + fast_sigmoid(r1.w);
    reinterpret_cast<float4*>(out)[(size_t)g * 16 + seg] = o;
}

// ---------------------------------------------------------------------------
extern "C" void kernel_launch(void* const* d_in, const int* in_sizes, int n_in,
                              void* d_out, int out_size) {
    const float* x  = (const float*)d_in[0];   // (B, N, D) f32
    const int2*  ep = (const int2*) d_in[1];   // (B, C, E, 2) i32 -> int2 pairs
    const float* wa = (const float*)d_in[2];   // (C, 2D, 1) f32
    float* out = (float*)d_out;                // (B, N, D) f32

    scores_kernel<<<(Bn * Nn * 32 + 255) / 256, 256>>>(x, wa);
    edge_kernel<<<(BCn * En + 255) / 256, 256>>>(ep);
    rcp_kernel<<<(BCn * Nn + 255) / 256, 256>>>();
    gather_kernel<<<(Bn * Nn * 16 + 255) / 256, 256>>>(x, out);
}

// round 13
// speedup vs baseline: 1.2204x; 1.0222x over previous
#include <cuda_runtime.h>
#include <cuda_bf16.h>
#include <cstdint>

// Problem constants (fixed by the dataset)
#define Bn 4
#define Nn 10000
#define Dn 64
#define Cn 2
#define En 160000
#define EPSc 1e-10f
#define BCn (Bn * Cn)
#define CAP 64           // bucket capacity per destination node (mean count = 16)

// Static scratch (no allocation allowed)
__device__ float  g_s1[BCn * Nn];              // node scores (dst half)
__device__ float  g_s2[BCn * Nn];              // node scores (src half)
__device__ float  g_denom[BCn * Nn];           // segment sum of e by idx0
__device__ float  g_rdenom[BCn * Nn];          // 1 / (denom + eps)
__device__ int    g_cnt[BCn * Nn];             // edges per destination node
__device__ float2 g_bucket[(size_t)BCn * Nn * CAP];  // (idx1 bits, e) slots (41 MB)

__device__ __forceinline__ float fast_tanh(float x) {
    float y;
    asm("tanh.approx.f32 %0, %1;" : "=f"(y) : "f"(x));
    return y;
}
__device__ __forceinline__ float fast_sigmoid(float x) {
    return 0.5f * fast_tanh(0.5f * x) + 0.5f;
}
// clamp any data-derived index into [0, Nn)
__device__ __forceinline__ int clamp_idx(int i) {
    unsigned u = (unsigned)i;
    return (u < (unsigned)Nn) ? (int)u : 0;
}

// ---------------------------------------------------------------------------
// K1: per-node scores; also zeroes denom/cnt (first 80K threads).
__global__ void scores_kernel(const float* __restrict__ x,
                              const float* __restrict__ wa) {
    int tg = blockIdx.x * blockDim.x + threadIdx.x;
    if (tg < BCn * Nn) {                     // fused zero pass
        g_denom[tg] = 0.f;
        g_cnt[tg] = 0;
    }
    int w = tg >> 5;
    int lane = threadIdx.x & 31;
    if (w >= Bn * Nn) return;
    int b = w / Nn;
    int n = w - b * Nn;

    float2 xv = reinterpret_cast<const float2*>(x + (size_t)(b * Nn + n) * Dn)[lane];

#pragma unroll
    for (int c = 0; c < Cn; c++) {
        float2 w1 = reinterpret_cast<const float2*>(wa + c * 2 * Dn)[lane];
        float2 w2 = reinterpret_cast<const float2*>(wa + c * 2 * Dn + Dn)[lane];
        float p1 = xv.x * w1.x + xv.y * w1.y;
        float p2 = xv.x * w2.x + xv.y * w2.y;
#pragma unroll
        for (int o = 16; o; o >>= 1) {
            p1 += __shfl_xor_sync(0xffffffffu, p1, o);
            p2 += __shfl_xor_sync(0xffffffffu, p2, o);
        }
        if (lane == 0) {
            g_s1[(b * Cn + c) * Nn + n] = p1;
            g_s2[(b * Cn + c) * Nn + n] = p2;
        }
    }
}

// ---------------------------------------------------------------------------
// K2: single edge pass: exp, denom accumulation, and bucket placement.
__global__ void edge_kernel(const int2* __restrict__ ep) {
    int t = blockIdx.x * blockDim.x + threadIdx.x;
    if (t >= BCn * En) return;
    int bc = t / En;
    int2 p = ep[t];                         // p.x = idx0 (dst), p.y = idx1 (src)
    int i0 = clamp_idx(p.x);
    int i1 = clamp_idx(p.y);
    float sc = g_s1[bc * Nn + i1] + g_s2[bc * Nn + i0];
    sc = sc >= 0.f ? sc : 0.2f * sc;        // leaky_relu(0.2)
    float ev = __expf(sc);
    int node = bc * Nn + i0;
    atomicAdd(&g_denom[node], ev);
    int pos = atomicAdd(&g_cnt[node], 1);
    if (pos < CAP)                          // overflow prob ~1e-24; safety clamp
        g_bucket[((size_t)node << 6) + pos] = make_float2(__int_as_float(i1), ev);
}

// ---------------------------------------------------------------------------
// K2b: reciprocal table: rdenom = 1 / (denom + eps). 80K threads, ~2us.
__global__ void rcp_kernel() {
    int t = blockIdx.x * blockDim.x + threadIdx.x;
    if (t < BCn * Nn)
        g_rdenom[t] = __fdividef(1.f, g_denom[t] + EPSc);
}

// ---------------------------------------------------------------------------
// K3: gather + sigmoid. ONE WARP per (b, n): lanes 0-15 = channel 0,
// lanes 16-31 = channel 1. Warp-private smem staging (__syncwarp only),
// per-thread loop bound = own channel's cnt (no cross-channel padding).
// Hot loop: LDS (16-lane broadcast) + LDG.128 + FMA. ~30 regs -> high occ.
__global__ __launch_bounds__(256) void gather_kernel(const float* __restrict__ x,
                                                     float* __restrict__ out) {
    __shared__ float2 sh[8][Cn][CAP];                // 8 KB per block
    int t = blockIdx.x * blockDim.x + threadIdx.x;
    int w = t >> 5;                                  // (b, n) group, 40000 total
    if (w >= Bn * Nn) return;
    int lane = threadIdx.x & 31;
    int wl = threadIdx.x >> 5;                       // warp index in block
    int ch = lane >> 4;                              // channel 0 or 1
    int seg = lane & 15;                             // float4 segment of the row
    int b = w / Nn;
    int n = w - b * Nn;
    int bc = b * Cn + ch;
    int node = bc * Nn + n;
    const float4* x4 = reinterpret_cast<const float4*>(x) + (size_t)b * Nn * 16;

    // ---- Phase 1: stage this channel's pairs with precomputed alpha ----
    int cnt = min(max(g_cnt[node], 0), CAP);
    {
        const float2* pairs = g_bucket + ((size_t)node << 6);
        const float* rden = g_rdenom + bc * Nn;
#pragma unroll
        for (int j = 0; j < 4; j++) {
            int slot = seg + j * 16;
            float2 st = make_float2(__int_as_float(0), 0.f);
            if (slot < cnt) {
                float2 pr = pairs[slot];
                int i1 = clamp_idx(__float_as_int(pr.x));
                st = make_float2(__int_as_float(i1), pr.y * rden[i1]);
            }
            sh[wl][ch][slot] = st;
        }
    }
    __syncwarp();

    // ---- Phase 2: gather own channel (zero-padded smem; <=3 wasted slots) ----
    const float2* my = &sh[wl][ch][0];
    float4 ae = make_float4(0.f, 0.f, 0.f, 0.f);
    float4 ao = make_float4(0.f, 0.f, 0.f, 0.f);
    for (int base = 0; base < cnt; base += 4) {
#pragma unroll
        for (int k = 0; k < 4; k++) {
            float2 pr = my[base + k];                // broadcast within 16 lanes
            float4 v = x4[(size_t)__float_as_int(pr.x) * 16 + seg];
            if (k & 1) {
                ao.x = fmaf(pr.y, v.x, ao.x);
                ao.y = fmaf(pr.y, v.y, ao.y);
                ao.z = fmaf(pr.y, v.z, ao.z);
                ao.w = fmaf(pr.y, v.w, ao.w);
            } else {
                ae.x = fmaf(pr.y, v.x, ae.x);
                ae.y = fmaf(pr.y, v.y, ae.y);
                ae.z = fmaf(pr.y, v.z, ae.z);
                ae.w = fmaf(pr.y, v.w, ae.w);
            }
        }
    }

    // ---- Epilogue: sigmoid, combine channels via shfl, lanes ch==0 store ----
    float sx = fast_sigmoid(ae.x + ao.x);
    float sy = fast_sigmoid(ae.y + ao.y);
    float sz = fast_sigmoid(ae.z + ao.z);
    float sw = fast_sigmoid(ae.w + ao.w);
    sx += __shfl_xor_sync(0xffffffffu, sx, 16);
    sy += __shfl_xor_sync(0xffffffffu, sy, 16);
    sz += __shfl_xor_sync(0xffffffffu, sz, 16);
    sw += __shfl_xor_sync(0xffffffffu, sw, 16);
    if (ch == 0)
        reinterpret_cast<float4*>(out)[(size_t)w * 16 + seg] =
            make_float4(sx, sy, sz, sw);
}

// ---------------------------------------------------------------------------
extern "C" void kernel_launch(void* const* d_in, const int* in_sizes, int n_in,
                              void* d_out, int out_size) {
    const float* x  = (const float*)d_in[0];   // (B, N, D) f32
    const int2*  ep = (const int2*) d_in[1];   // (B, C, E, 2) i32 -> int2 pairs
    const float* wa = (const float*)d_in[2];   // (C, 2D, 1) f32
    float* out = (float*)d_out;                // (B, N, D) f32

    scores_kernel<<<(Bn * Nn * 32 + 255) / 256, 256>>>(x, wa);
    edge_kernel<<<(BCn * En + 255) / 256, 256>>>(ep);
    rcp_kernel<<<(BCn * Nn + 255) / 256, 256>>>();
    gather_kernel<<<(Bn * Nn * 32 + 255) / 256, 256>>>(x, out);
}

// round 14
// speedup vs baseline: 1.3295x; 1.0894x over previous
#include <cuda_runtime.h>
#include <cuda_bf16.h>
#include <cuda_fp16.h>
#include <cstdint>

// Problem constants (fixed by the dataset)
#define Bn 4
#define Nn 10000
#define Dn 64
#define Cn 2
#define En 160000
#define EPSc 1e-10f
#define BCn (Bn * Cn)
#define CAP 64           // bucket capacity per destination node (mean count = 16)

// Static scratch (no allocation allowed)
__device__ float   g_s1[BCn * Nn];             // node scores (dst half)
__device__ float   g_s2[BCn * Nn];             // node scores (src half)
__device__ float   g_denom[BCn * Nn];          // segment sum of e by idx0
__device__ float   g_rdenom[BCn * Nn];         // 1 / (denom + eps)
__device__ int     g_cnt[BCn * Nn];            // edges per destination node
__device__ float2  g_bucket[(size_t)BCn * Nn * CAP]; // (idx1 bits, e) slots (41 MB)
__device__ __half2 g_xh[(size_t)Bn * Nn * (Dn / 2)]; // fp16 mirror of x (5 MB)

__device__ __forceinline__ float fast_tanh(float x) {
    float y;
    asm("tanh.approx.f32 %0, %1;" : "=f"(y) : "f"(x));
    return y;
}
__device__ __forceinline__ float fast_sigmoid(float x) {
    return 0.5f * fast_tanh(0.5f * x) + 0.5f;
}
// clamp any data-derived index into [0, Nn)
__device__ __forceinline__ int clamp_idx(int i) {
    unsigned u = (unsigned)i;
    return (u < (unsigned)Nn) ? (int)u : 0;
}

// ---------------------------------------------------------------------------
// K1: per-node scores; also zeroes denom/cnt and writes the fp16 x mirror.
__global__ void scores_kernel(const float* __restrict__ x,
                              const float* __restrict__ wa) {
    int tg = blockIdx.x * blockDim.x + threadIdx.x;
    if (tg < BCn * Nn) {                     // fused zero pass
        g_denom[tg] = 0.f;
        g_cnt[tg] = 0;
    }
    int w = tg >> 5;
    int lane = threadIdx.x & 31;
    if (w >= Bn * Nn) return;
    int b = w / Nn;
    int n = w - b * Nn;

    float2 xv = reinterpret_cast<const float2*>(x + (size_t)(b * Nn + n) * Dn)[lane];
    // free fp16 mirror write (row already in registers)
    g_xh[(size_t)(b * Nn + n) * 32 + lane] = __float22half2_rn(xv);

#pragma unroll
    for (int c = 0; c < Cn; c++) {
        float2 w1 = reinterpret_cast<const float2*>(wa + c * 2 * Dn)[lane];
        float2 w2 = reinterpret_cast<const float2*>(wa + c * 2 * Dn + Dn)[lane];
        float p1 = xv.x * w1.x + xv.y * w1.y;
        float p2 = xv.x * w2.x + xv.y * w2.y;
#pragma unroll
        for (int o = 16; o; o >>= 1) {
            p1 += __shfl_xor_sync(0xffffffffu, p1, o);
            p2 += __shfl_xor_sync(0xffffffffu, p2, o);
        }
        if (lane == 0) {
            g_s1[(b * Cn + c) * Nn + n] = p1;
            g_s2[(b * Cn + c) * Nn + n] = p2;
        }
    }
}

// ---------------------------------------------------------------------------
// K2: single edge pass: exp, denom accumulation, and bucket placement.
__global__ void edge_kernel(const int2* __restrict__ ep) {
    int t = blockIdx.x * blockDim.x + threadIdx.x;
    if (t >= BCn * En) return;
    int bc = t / En;
    int2 p = ep[t];                         // p.x = idx0 (dst), p.y = idx1 (src)
    int i0 = clamp_idx(p.x);
    int i1 = clamp_idx(p.y);
    float sc = g_s1[bc * Nn + i1] + g_s2[bc * Nn + i0];
    sc = sc >= 0.f ? sc : 0.2f * sc;        // leaky_relu(0.2)
    float ev = __expf(sc);
    int node = bc * Nn + i0;
    atomicAdd(&g_denom[node], ev);
    int pos = atomicAdd(&g_cnt[node], 1);
    if (pos < CAP)                          // overflow prob ~1e-24; safety clamp
        g_bucket[((size_t)node << 6) + pos] = make_float2(__int_as_float(i1), ev);
}

// ---------------------------------------------------------------------------
// K2b: reciprocal table: rdenom = 1 / (denom + eps). 80K threads, ~2us.
__global__ void rcp_kernel() {
    int t = blockIdx.x * blockDim.x + threadIdx.x;
    if (t < BCn * Nn)
        g_rdenom[t] = __fdividef(1.f, g_denom[t] + EPSc);
}

// ---------------------------------------------------------------------------
// K3: gather + sigmoid. ONE WARP per (b, n): lanes 0-15 = channel 0,
// lanes 16-31 = channel 1. Warp-private smem staging (__syncwarp only).
// Hot loop reads the fp16 x mirror: LDG.64 per lane (128B per row) — half
// the traffic of the fp32 path. Accumulation stays fp32.
__global__ __launch_bounds__(256) void gather_kernel(float* __restrict__ out) {
    __shared__ float2 sh[8][Cn][CAP];                // 8 KB per block
    int t = blockIdx.x * blockDim.x + threadIdx.x;
    int w = t >> 5;                                  // (b, n) group, 40000 total
    if (w >= Bn * Nn) return;
    int lane = threadIdx.x & 31;
    int wl = threadIdx.x >> 5;                       // warp index in block
    int ch = lane >> 4;                              // channel 0 or 1
    int seg = lane & 15;                             // 4-float segment of the row
    int b = w / Nn;
    int n = w - b * Nn;
    int bc = b * Cn + ch;
    int node = bc * Nn + n;
    const __half2* xh = g_xh + (size_t)b * Nn * 32;

    // ---- Phase 1: stage this channel's pairs with precomputed alpha ----
    int cnt = min(max(g_cnt[node], 0), CAP);
    {
        const float2* pairs = g_bucket + ((size_t)node << 6);
        const float* rden = g_rdenom + bc * Nn;
#pragma unroll
        for (int j = 0; j < 4; j++) {
            int slot = seg + j * 16;
            float2 st = make_float2(__int_as_float(0), 0.f);
            if (slot < cnt) {
                float2 pr = pairs[slot];
                int i1 = clamp_idx(__float_as_int(pr.x));
                st = make_float2(__int_as_float(i1), pr.y * rden[i1]);
            }
            sh[wl][ch][slot] = st;
        }
    }
    __syncwarp();

    // ---- Phase 2: gather own channel from the fp16 mirror ----
    const float2* my = &sh[wl][ch][0];
    float4 ae = make_float4(0.f, 0.f, 0.f, 0.f);
    float4 ao = make_float4(0.f, 0.f, 0.f, 0.f);
    for (int base = 0; base < cnt; base += 4) {
#pragma unroll
        for (int k = 0; k < 4; k++) {
            float2 pr = my[base + k];                // broadcast within 16 lanes
            int i1 = __float_as_int(pr.x);
            uint2 u = *reinterpret_cast<const uint2*>(
                xh + (size_t)i1 * 32 + (seg << 1));  // LDG.64: 4 halfs
            __half2 h0 = *reinterpret_cast<__half2*>(&u.x);
            __half2 h1 = *reinterpret_cast<__half2*>(&u.y);
            float2 f0 = __half22float2(h0);
            float2 f1 = __half22float2(h1);
            if (k & 1) {
                ao.x = fmaf(pr.y, f0.x, ao.x);
                ao.y = fmaf(pr.y, f0.y, ao.y);
                ao.z = fmaf(pr.y, f1.x, ao.z);
                ao.w = fmaf(pr.y, f1.y, ao.w);
            } else {
                ae.x = fmaf(pr.y, f0.x, ae.x);
                ae.y = fmaf(pr.y, f0.y, ae.y);
                ae.z = fmaf(pr.y, f1.x, ae.z);
                ae.w = fmaf(pr.y, f1.y, ae.w);
            }
        }
    }

    // ---- Epilogue: sigmoid, combine channels via shfl, lanes ch==0 store ----
    float sx = fast_sigmoid(ae.x + ao.x);
    float sy = fast_sigmoid(ae.y + ao.y);
    float sz = fast_sigmoid(ae.z + ao.z);
    float sw = fast_sigmoid(ae.w + ao.w);
    sx += __shfl_xor_sync(0xffffffffu, sx, 16);
    sy += __shfl_xor_sync(0xffffffffu, sy, 16);
    sz += __shfl_xor_sync(0xffffffffu, sz, 16);
    sw += __shfl_xor_sync(0xffffffffu, sw, 16);
    if (ch == 0)
        reinterpret_cast<float4*>(out)[(size_t)w * 16 + seg] =
            make_float4(sx, sy, sz, sw);
}

// ---------------------------------------------------------------------------
extern "C" void kernel_launch(void* const* d_in, const int* in_sizes, int n_in,
                              void* d_out, int out_size) {
    const float* x  = (const float*)d_in[0];   // (B, N, D) f32
    const int2*  ep = (const int2*) d_in[1];   // (B, C, E, 2) i32 -> int2 pairs
    const float* wa = (const float*)d_in[2];   // (C, 2D, 1) f32
    float* out = (float*)d_out;                // (B, N, D) f32

    scores_kernel<<<(Bn * Nn * 32 + 255) / 256, 256>>>(x, wa);
    edge_kernel<<<(BCn * En + 255) / 256, 256>>>(ep);
    rcp_kernel<<<(BCn * Nn + 255) / 256, 256>>>();
    gather_kernel<<<(Bn * Nn * 32 + 255) / 256, 256>>>(out);
}

// round 15
// speedup vs baseline: 1.3815x; 1.0392x over previous
#include <cuda_runtime.h>
#include <cuda_bf16.h>
#include <cuda_fp16.h>
#include <cstdint>

// Problem constants (fixed by the dataset)
#define Bn 4
#define Nn 10000
#define Dn 64
#define Cn 2
#define En 160000
#define EPSc 1e-10f
#define BCn (Bn * Cn)
#define CAP 64           // bucket capacity per destination node (mean count = 16)

// Static scratch (no allocation allowed)
__device__ float   g_s1[BCn * Nn];             // node scores (dst half)
__device__ float   g_s2[BCn * Nn];             // node scores (src half)
__device__ float   g_denom[BCn * Nn];          // segment sum of e by idx0
__device__ int     g_cnt[BCn * Nn];            // edges per destination node
__device__ float2  g_bucket[(size_t)BCn * Nn * CAP]; // (idx1 bits, e) slots (41 MB)
__device__ __half2 g_xh[(size_t)Bn * Nn * (Dn / 2)]; // fp16 mirror of x (5 MB)

__device__ __forceinline__ float fast_tanh(float x) {
    float y;
    asm("tanh.approx.f32 %0, %1;" : "=f"(y) : "f"(x));
    return y;
}
__device__ __forceinline__ float fast_sigmoid(float x) {
    return 0.5f * fast_tanh(0.5f * x) + 0.5f;
}
// clamp any data-derived index into [0, Nn)
__device__ __forceinline__ int clamp_idx(int i) {
    unsigned u = (unsigned)i;
    return (u < (unsigned)Nn) ? (int)u : 0;
}

// ---------------------------------------------------------------------------
// K1: per-node scores; also zeroes denom/cnt and writes the fp16 x mirror.
__global__ void scores_kernel(const float* __restrict__ x,
                              const float* __restrict__ wa) {
    int tg = blockIdx.x * blockDim.x + threadIdx.x;
    if (tg < BCn * Nn) {                     // fused zero pass
        g_denom[tg] = 0.f;
        g_cnt[tg] = 0;
    }
    int w = tg >> 5;
    int lane = threadIdx.x & 31;
    if (w >= Bn * Nn) return;
    int b = w / Nn;
    int n = w - b * Nn;

    float2 xv = reinterpret_cast<const float2*>(x + (size_t)(b * Nn + n) * Dn)[lane];
    // free fp16 mirror write (row already in registers)
    g_xh[(size_t)(b * Nn + n) * 32 + lane] = __float22half2_rn(xv);

#pragma unroll
    for (int c = 0; c < Cn; c++) {
        float2 w1 = reinterpret_cast<const float2*>(wa + c * 2 * Dn)[lane];
        float2 w2 = reinterpret_cast<const float2*>(wa + c * 2 * Dn + Dn)[lane];
        float p1 = xv.x * w1.x + xv.y * w1.y;
        float p2 = xv.x * w2.x + xv.y * w2.y;
#pragma unroll
        for (int o = 16; o; o >>= 1) {
            p1 += __shfl_xor_sync(0xffffffffu, p1, o);
            p2 += __shfl_xor_sync(0xffffffffu, p2, o);
        }
        if (lane == 0) {
            g_s1[(b * Cn + c) * Nn + n] = p1;
            g_s2[(b * Cn + c) * Nn + n] = p2;
        }
    }
}

// ---------------------------------------------------------------------------
// K2: single edge pass: exp, denom accumulation, and bucket placement.
__global__ void edge_kernel(const int2* __restrict__ ep) {
    int t = blockIdx.x * blockDim.x + threadIdx.x;
    if (t >= BCn * En) return;
    int bc = t / En;
    int2 p = ep[t];                         // p.x = idx0 (dst), p.y = idx1 (src)
    int i0 = clamp_idx(p.x);
    int i1 = clamp_idx(p.y);
    float sc = g_s1[bc * Nn + i1] + g_s2[bc * Nn + i0];
    sc = sc >= 0.f ? sc : 0.2f * sc;        // leaky_relu(0.2)
    float ev = __expf(sc);
    int node = bc * Nn + i0;
    atomicAdd(&g_denom[node], ev);
    int pos = atomicAdd(&g_cnt[node], 1);
    if (pos < CAP)                          // overflow prob ~1e-24; safety clamp
        g_bucket[((size_t)node << 6) + pos] = make_float2(__int_as_float(i1), ev);
}

// ---------------------------------------------------------------------------
// K3: gather + sigmoid. One warp = 2 nodes; lane = (sub, ch, s8):
// lanes split 2 nodes x 2 channels x 8 segments of 8 halfs (LDG.128/row).
// Staging computes alpha = e / (denom[i1] + eps) directly (no rcp kernel).
// Hot loop per row: LDS.64 + LDG.128 + converts + 8 FMA across 8 lanes.
__global__ __launch_bounds__(256) void gather_kernel(float* __restrict__ out) {
    __shared__ float2 sh[8][2][Cn][CAP];             // 16 KB per block
    int t = blockIdx.x * blockDim.x + threadIdx.x;
    int w = t >> 5;                                  // warp id, 20000 total
    if (w >= Bn * Nn / 2) return;
    int lane = threadIdx.x & 31;
    int wl = threadIdx.x >> 5;                       // warp index in block
    int sub = lane >> 4;                             // node within the pair
    int ch = (lane >> 3) & 1;                        // channel 0 or 1
    int s8 = lane & 7;                               // 8-half segment of the row
    int g = 2 * w + sub;                             // (b, n) node id
    int b = g / Nn;
    int n = g - b * Nn;
    int bc = b * Cn + ch;
    int node = bc * Nn + n;

    // ---- Phase 1: stage (i1, alpha) for own (node, ch); zero-padded ----
    int cnt = min(max(g_cnt[node], 0), CAP);
    {
        const float2* pairs = g_bucket + ((size_t)node << 6);
        const float* den = g_denom + bc * Nn;
#pragma unroll
        for (int j = 0; j < 8; j++) {
            int slot = s8 + j * 8;
            float2 st = make_float2(__int_as_float(0), 0.f);
            if (slot < cnt) {
                float2 pr = pairs[slot];
                int i1 = clamp_idx(__float_as_int(pr.x));
                st = make_float2(__int_as_float(i1),
                                 __fdividef(pr.y, den[i1] + EPSc));
            }
            sh[wl][sub][ch][slot] = st;
        }
    }
    __syncwarp();

    // ---- Phase 2: gather own channel; 8 halfs per lane per row ----
    const float2* my = &sh[wl][sub][ch][0];
    const uint4* xrow = reinterpret_cast<const uint4*>(g_xh + (size_t)b * Nn * 32);
    float4 A = make_float4(0.f, 0.f, 0.f, 0.f);
    float4 Bv = make_float4(0.f, 0.f, 0.f, 0.f);
    for (int base = 0; base < cnt; base += 4) {
#pragma unroll
        for (int k = 0; k < 4; k++) {
            float2 pr = my[base + k];                // broadcast within 8 lanes
            int i1 = __float_as_int(pr.x);
            uint4 u = xrow[(size_t)i1 * 8 + s8];     // LDG.128: 8 halfs
            float2 f0 = __half22float2(*reinterpret_cast<__half2*>(&u.x));
            float2 f1 = __half22float2(*reinterpret_cast<__half2*>(&u.y));
            float2 f2 = __half22float2(*reinterpret_cast<__half2*>(&u.z));
            float2 f3 = __half22float2(*reinterpret_cast<__half2*>(&u.w));
            A.x = fmaf(pr.y, f0.x, A.x);
            A.y = fmaf(pr.y, f0.y, A.y);
            A.z = fmaf(pr.y, f1.x, A.z);
            A.w = fmaf(pr.y, f1.y, A.w);
            Bv.x = fmaf(pr.y, f2.x, Bv.x);
            Bv.y = fmaf(pr.y, f2.y, Bv.y);
            Bv.z = fmaf(pr.y, f3.x, Bv.z);
            Bv.w = fmaf(pr.y, f3.y, Bv.w);
        }
    }

    // ---- Epilogue: sigmoid, combine channels (shfl_xor 8), store 8 floats ----
    float4 sA, sB;
    sA.x = fast_sigmoid(A.x);  sA.y = fast_sigmoid(A.y);
    sA.z = fast_sigmoid(A.z);  sA.w = fast_sigmoid(A.w);
    sB.x = fast_sigmoid(Bv.x); sB.y = fast_sigmoid(Bv.y);
    sB.z = fast_sigmoid(Bv.z); sB.w = fast_sigmoid(Bv.w);
    sA.x += __shfl_xor_sync(0xffffffffu, sA.x, 8);
    sA.y += __shfl_xor_sync(0xffffffffu, sA.y, 8);
    sA.z += __shfl_xor_sync(0xffffffffu, sA.z, 8);
    sA.w += __shfl_xor_sync(0xffffffffu, sA.w, 8);
    sB.x += __shfl_xor_sync(0xffffffffu, sB.x, 8);
    sB.y += __shfl_xor_sync(0xffffffffu, sB.y, 8);
    sB.z += __shfl_xor_sync(0xffffffffu, sB.z, 8);
    sB.w += __shfl_xor_sync(0xffffffffu, sB.w, 8);
    if (ch == 0) {
        float4* o = reinterpret_cast<float4*>(out) + (size_t)g * 16 + s8 * 2;
        o[0] = sA;
        o[1] = sB;
    }
}

// ---------------------------------------------------------------------------
extern "C" void kernel_launch(void* const* d_in, const int* in_sizes, int n_in,
                              void* d_out, int out_size) {
    const float* x  = (const float*)d_in[0];   // (B, N, D) f32
    const int2*  ep = (const int2*) d_in[1];   // (B, C, E, 2) i32 -> int2 pairs
    const float* wa = (const float*)d_in[2];   // (C, 2D, 1) f32
    float* out = (float*)d_out;                // (B, N, D) f32

    scores_kernel<<<(Bn * Nn * 32 + 255) / 256, 256>>>(x, wa);
    edge_kernel<<<(BCn * En + 255) / 256, 256>>>(ep);
    gather_kernel<<<(Bn * Nn / 2 * 32 + 255) / 256, 256>>>(out);
}